// round 4
// baseline (speedup 1.0000x reference)
#include <cuda_runtime.h>
#include <math.h>

#define Nn 8192
#define Dd 4
#define Ff 256
#define Hh 512
#define Aa 64
#define Ee (Nn*Dd)
#define G4 2048
#define NCTA 64

// ---------------- device scratch (no cudaMalloc allowed) ----------------
__device__ float g_preF[(size_t)Ee*G4];     // edges @ Wih_f^T + b_f
__device__ float g_preB[(size_t)Ee*G4];     // edges @ Wih_b^T + b_b
__device__ float g_u  [2][(size_t)Nn*G4];   // Whh @ h_node per node
__device__ float g_c  [2][(size_t)Nn*Hh];   // c_node per node
__device__ float g_arcA[(size_t)Ee*Hh];     // fwd arc_h (== ef, edge layout)
__device__ float g_arcB[(size_t)Ee*Hh];     // bwd arc_h at [node][slot]
__device__ float g_z  [2][(size_t)Nn*Dd*Aa];// attention preactivation accumulators
__device__ float g_hid[(size_t)Ee*Hh];      // decoder hidden
__device__ int   g_cz[2][Nn];
__device__ int   g_cu[2][Nn];

// ---------------- helpers ----------------
__device__ __forceinline__ int ld_acq(const int* p){
    int v; asm volatile("ld.acquire.gpu.b32 %0,[%1];":"=r"(v):"l"(p):"memory"); return v;
}
__device__ __forceinline__ void red_rel(int* p){
    asm volatile("red.release.gpu.global.add.s32 [%0], 1;"::"l"(p):"memory");
}
__device__ __forceinline__ float sigf(float x){ return 1.f/(1.f+expf(-x)); }

// ---------------- init: counters + z-seed (ba + x[:3] @ Wa[:,512:515]^T) ---
__global__ void init_kernel(const float* __restrict__ edges,
                            const float* __restrict__ Wa,
                            const float* __restrict__ ba)
{
    int idx = blockIdx.x*256 + threadIdx.x;        // 0 .. 2^22-1
    if (idx < Nn){
        g_cz[0][idx]=0; g_cz[1][idx]=0; g_cu[0][idx]=0; g_cu[1][idx]=0;
    }
    int dir = idx >> 21;
    int rem = idx & ((1<<21)-1);
    int i = rem >> 8;
    int d = (rem >> 6) & 3;
    int a = rem & 63;
    float z = ba[a];
    size_t e = 0; bool ok = true;
    if (dir == 0) e = (size_t)i*4 + d;
    else { int cn = i+1+d; if (cn < Nn) e = (size_t)cn*4 + d; else ok = false; }
    if (ok){
        const float* x  = edges + e*Ff;
        const float* wr = Wa + (size_t)a*(Hh+3) + Hh;
        z += x[0]*wr[0] + x[1]*wr[1] + x[2]*wr[2];
    }
    g_z[dir][((size_t)i*4 + d)*Aa + a] = z;
}

// ------------- SGEMM: C[M,Nc] = A[M,K] @ B[Nc,K]^T + bias (opt relu) -------
// mode 0: plain A.  mode 1: A rows are feat[e] = [ef[e] | eb[e]] gathered.
__global__ void __launch_bounds__(256) gemm_kernel(
    const float* __restrict__ A, const float* __restrict__ B,
    const float* __restrict__ bias, float* __restrict__ C,
    int M, int Nc, int K, int mode)
{
    __shared__ float sA[16][132];
    __shared__ float sB[16][132];
    int tid = threadIdx.x;
    int n0 = blockIdx.x * 128;
    int m0 = blockIdx.y * 128;
    int tx = tid & 15, ty = tid >> 4;
    float acc[8][8];
    #pragma unroll
    for (int ii=0; ii<8; ii++)
        #pragma unroll
        for (int jj=0; jj<8; jj++) acc[ii][jj] = 0.f;

    for (int k0 = 0; k0 < K; k0 += 16){
        #pragma unroll
        for (int u = 0; u < 2; u++){
            int v = tid + u*256;
            int row = v >> 2, kq = v & 3;
            float4 va;
            if (mode == 0){
                va = *(const float4*)(A + (size_t)(m0+row)*K + k0 + kq*4);
            } else {
                int e = m0 + row;
                int kk = k0 + kq*4;
                if (kk < Hh){
                    va = *(const float4*)(g_arcA + (size_t)e*Hh + kk);
                } else {
                    int d = e & 3, j = e >> 2;
                    if (j >= 1+d)
                        va = *(const float4*)(g_arcB + (size_t)(e - 4*(1+d))*Hh + (kk - Hh));
                    else
                        va = make_float4(0.f,0.f,0.f,0.f);
                }
            }
            sA[kq*4+0][row]=va.x; sA[kq*4+1][row]=va.y;
            sA[kq*4+2][row]=va.z; sA[kq*4+3][row]=va.w;
            float4 vb = *(const float4*)(B + (size_t)(n0+row)*K + k0 + kq*4);
            sB[kq*4+0][row]=vb.x; sB[kq*4+1][row]=vb.y;
            sB[kq*4+2][row]=vb.z; sB[kq*4+3][row]=vb.w;
        }
        __syncthreads();
        #pragma unroll
        for (int k=0; k<16; k++){
            float4 a0 = *(const float4*)&sA[k][ty*8];
            float4 a1 = *(const float4*)&sA[k][ty*8+4];
            float4 b0 = *(const float4*)&sB[k][tx*8];
            float4 b1 = *(const float4*)&sB[k][tx*8+4];
            float av[8] = {a0.x,a0.y,a0.z,a0.w,a1.x,a1.y,a1.z,a1.w};
            float bv[8] = {b0.x,b0.y,b0.z,b0.w,b1.x,b1.y,b1.z,b1.w};
            #pragma unroll
            for (int ii=0; ii<8; ii++)
                #pragma unroll
                for (int jj=0; jj<8; jj++)
                    acc[ii][jj] = fmaf(av[ii], bv[jj], acc[ii][jj]);
        }
        __syncthreads();
    }
    #pragma unroll
    for (int ii=0; ii<8; ii++){
        int m = m0 + ty*8 + ii;
        #pragma unroll
        for (int jj=0; jj<8; jj++){
            int n = n0 + tx*8 + jj;
            float v = acc[ii][jj] + bias[n];
            if (mode == 1) v = fmaxf(v, 0.f);
            C[(size_t)m*Nc + n] = v;
        }
    }
}

// ---------------- persistent bidirectional recurrence ----------------------
__global__ void __launch_bounds__(256, 1) recur_kernel(
    const float* __restrict__ Whh_f, const float* __restrict__ Whh_b,
    const float* __restrict__ Wa, const float* __restrict__ Wao,
    const float* __restrict__ bao)
{
    const int dir = blockIdx.x >> 6;
    const int ct  = blockIdx.x & 63;
    const int tid = threadIdx.x;
    const int w = tid >> 5, l = tid & 31;

    const float* Whh = dir ? Whh_b : Whh_f;
    const float* preX = dir ? g_preB : g_preF;
    float* uArr = g_u[dir];
    float* cArr = g_c[dir];
    float* arc  = dir ? g_arcB : g_arcA;
    float* zArr = g_z[dir];
    int* cz = g_cz[dir];
    int* cu = g_cu[dir];

    __shared__ float sWa[8][64];
    __shared__ float sWao[64];
    __shared__ float sbao;
    __shared__ float h_s[4][8];
    __shared__ float carc_s[4][8];
    __shared__ float zs[256];
    __shared__ float logit_s[4];

    for (int x = tid; x < 512; x += 256){
        int q = x >> 6, a = x & 63;
        sWa[q][a] = Wa[(size_t)a*(Hh+3) + ct*8 + q];
    }
    if (tid < 64) sWao[tid] = Wao[tid];
    if (tid == 0) sbao = bao[0];

    // register-resident Whh slice: warp w owns rows R0..R0+3, lane l owns k=l*16..+15
    const int R0 = ct*32 + w*4;
    float4 wreg[4][4];
    #pragma unroll
    for (int r=0; r<4; r++)
        #pragma unroll
        for (int q=0; q<4; q++)
            wreg[r][q] = *(const float4*)(Whh + (size_t)(R0+r)*Hh + l*16 + q*4);
    __syncthreads();

    for (int t = 0; t < Nn; t++){
        const int i = dir ? (Nn-1-t) : t;
        if (t > 0){
            int ip = dir ? i+1 : i-1;
            if (tid == 0) while (ld_acq(&cu[ip]) < NCTA) {}
            __syncthreads();
        }

        // -------- Phase A: cell for this CTA's 8 h-elements x 4 arcs (warp 0)
        if (w == 0){
            int d = l >> 3, q = l & 7;
            int jj = ct*8 + q;
            bool valid = dir ? (i+1+d < Nn) : (i-1-d >= 0);
            float ha = 0.f, ca = 0.f;
            if (valid){
                int p = dir ? (i+1+d) : (i-1-d);
                size_t e = dir ? ((size_t)(i+1+d)*4 + d) : ((size_t)i*4 + d);
                const float* pr = preX + e*G4;
                const float* uu = uArr + (size_t)p*G4;
                float gi = pr[jj]        + __ldcg(uu + jj);
                float gf = pr[Hh+jj]     + __ldcg(uu + Hh+jj);
                float gg = pr[2*Hh+jj]   + __ldcg(uu + 2*Hh+jj);
                float go = pr[3*Hh+jj]   + __ldcg(uu + 3*Hh+jj);
                float cp = __ldcg(cArr + (size_t)p*Hh + jj);
                ca = sigf(gf)*cp + sigf(gi)*tanhf(gg);
                ha = sigf(go)*tanhf(ca);
            }
            h_s[d][q] = ha; carc_s[d][q] = ca;
            arc[((size_t)i*4 + d)*Hh + jj] = ha;
        }
        __syncthreads();

        // -------- Phase A-z: partial attention preactivations (all threads)
        {
            int d = tid >> 6, a = tid & 63;
            float v = 0.f;
            #pragma unroll
            for (int q=0; q<8; q++) v = fmaf(sWa[q][a], h_s[d][q], v);
            atomicAdd(&zArr[(size_t)i*256 + d*64 + a], v);
        }
        __syncthreads();
        if (tid == 0){
            red_rel(&cz[i]);
            while (ld_acq(&cz[i]) < NCTA) {}
        }
        __syncthreads();

        // -------- Phase B: logits + softmax weights (redundant per CTA)
        zs[tid] = __ldcg(&zArr[(size_t)i*256 + tid]);
        __syncthreads();
        if (tid < 4){
            float s = sbao;
            #pragma unroll
            for (int a=0; a<64; a++) s = fmaf(fmaxf(zs[tid*64+a], 0.f), sWao[a], s);
            logit_s[tid] = tanhf(s);
        }
        __syncthreads();
        float wgt[4];
        {
            bool vld[4]; float m = -1e30f; int nv = 0;
            #pragma unroll
            for (int d=0; d<4; d++){
                vld[d] = dir ? (i+1+d < Nn) : (i-1-d >= 0);
                if (vld[d]){ m = fmaxf(m, logit_s[d]); nv++; }
            }
            float ssum = 0.f;
            #pragma unroll
            for (int d=0; d<4; d++){
                float ev = vld[d] ? expf(logit_s[d]-m) : 0.f;
                wgt[d] = ev; ssum += ev;
            }
            if (nv){
                float inv = 1.f/ssum;
                #pragma unroll
                for (int d=0; d<4; d++) wgt[d] *= inv;
            }
        }

        // -------- Phase C: h_node slice (per lane k=l*16..+15), u = Whh@h_node
        float4 hn[4];
        #pragma unroll
        for (int q=0; q<4; q++) hn[q] = make_float4(0.f,0.f,0.f,0.f);
        #pragma unroll
        for (int d=0; d<4; d++){
            const float4* src = (const float4*)(arc + ((size_t)i*4 + d)*Hh + l*16);
            float wd = wgt[d];
            #pragma unroll
            for (int q=0; q<4; q++){
                float4 s = __ldcg(src + q);
                hn[q].x = fmaf(wd, s.x, hn[q].x);
                hn[q].y = fmaf(wd, s.y, hn[q].y);
                hn[q].z = fmaf(wd, s.z, hn[q].z);
                hn[q].w = fmaf(wd, s.w, hn[q].w);
            }
        }
        float acc[4] = {0.f,0.f,0.f,0.f};
        #pragma unroll
        for (int r=0; r<4; r++)
            #pragma unroll
            for (int q=0; q<4; q++){
                acc[r] = fmaf(wreg[r][q].x, hn[q].x, acc[r]);
                acc[r] = fmaf(wreg[r][q].y, hn[q].y, acc[r]);
                acc[r] = fmaf(wreg[r][q].z, hn[q].z, acc[r]);
                acc[r] = fmaf(wreg[r][q].w, hn[q].w, acc[r]);
            }
        #pragma unroll
        for (int off=16; off; off >>= 1){
            #pragma unroll
            for (int r=0; r<4; r++)
                acc[r] += __shfl_xor_sync(0xffffffffu, acc[r], off);
        }
        if (l < 4){
            float outv = (l==0)?acc[0]:(l==1)?acc[1]:(l==2)?acc[2]:acc[3];
            uArr[(size_t)i*G4 + R0 + l] = outv;
        }
        if (tid < 8){
            float c = 0.f;
            #pragma unroll
            for (int d=0; d<4; d++) c = fmaf(wgt[d], carc_s[d][tid], c);
            cArr[(size_t)i*Hh + ct*8 + tid] = c;
        }
        __syncthreads();
        if (tid == 0) red_rel(&cu[i]);
    }
}

// ---------------- final: out[e] = hid[e] . Wdo + bdo --------------------
__global__ void final_kernel(const float* __restrict__ Wdo,
                             const float* __restrict__ bdo,
                             float* __restrict__ out)
{
    int gw = (blockIdx.x*blockDim.x + threadIdx.x) >> 5;
    int l = threadIdx.x & 31;
    if (gw >= Ee) return;
    const float* h = g_hid + (size_t)gw*Hh;
    float s = 0.f;
    #pragma unroll
    for (int q=0; q<16; q++) s = fmaf(h[l + q*32], Wdo[l + q*32], s);
    #pragma unroll
    for (int off=16; off; off >>= 1) s += __shfl_xor_sync(0xffffffffu, s, off);
    if (l == 0) out[gw] = s + bdo[0];
}

// ---------------- launch --------------------------------------------------
extern "C" void kernel_launch(void* const* d_in, const int* in_sizes, int n_in,
                              void* d_out, int out_size)
{
    const float* edges = (const float*)d_in[0];
    const float* Wih_f = (const float*)d_in[1];
    const float* Whh_f = (const float*)d_in[2];
    const float* b_f   = (const float*)d_in[3];
    const float* Wih_b = (const float*)d_in[4];
    const float* Whh_b = (const float*)d_in[5];
    const float* b_b   = (const float*)d_in[6];
    const float* Wa    = (const float*)d_in[7];
    const float* ba    = (const float*)d_in[8];
    const float* Wao   = (const float*)d_in[9];
    const float* bao   = (const float*)d_in[10];
    const float* Wd    = (const float*)d_in[11];
    const float* bd    = (const float*)d_in[12];
    const float* Wdo   = (const float*)d_in[13];
    const float* bdo   = (const float*)d_in[14];
    float* out = (float*)d_out;

    float *preF, *preB, *hid;
    cudaGetSymbolAddress((void**)&preF, g_preF);
    cudaGetSymbolAddress((void**)&preB, g_preB);
    cudaGetSymbolAddress((void**)&hid,  g_hid);

    // 1. counters + z seed
    init_kernel<<<16384, 256>>>(edges, Wa, ba);
    // 2. input-side GEMMs: pre = edges @ Wih^T + b
    gemm_kernel<<<dim3(G4/128, Ee/128), 256>>>(edges, Wih_f, b_f, preF, Ee, G4, Ff, 0);
    gemm_kernel<<<dim3(G4/128, Ee/128), 256>>>(edges, Wih_b, b_b, preB, Ee, G4, Ff, 0);
    // 3. bidirectional recurrence (persistent, 128 CTAs)
    recur_kernel<<<2*NCTA, 256>>>(Whh_f, Whh_b, Wa, Wao, bao);
    // 4. decoder GEMM: hid = relu(feat @ Wd^T + bd), feat gathered from arcs
    gemm_kernel<<<dim3(Hh/128, Ee/128), 256>>>(nullptr, Wd, bd, hid, Ee, Hh, 2*Hh, 1);
    // 5. output projection
    final_kernel<<<(Ee*32)/256, 256>>>(Wdo, bdo, out);
}

// round 5
// speedup vs baseline: 1.0263x; 1.0263x over previous
#include <cuda_runtime.h>
#include <math.h>

#define Nn 8192
#define Dd 4
#define Ff 256
#define Hh 512
#define Aa 64
#define Ee (Nn*Dd)
#define G4 2048
#define NCTA 64

// ---------------- device scratch (no cudaMalloc allowed) ----------------
__device__ float g_preF[(size_t)Ee*G4];     // edges @ Wih_f^T + b_f
__device__ float g_preB[(size_t)Ee*G4];     // edges @ Wih_b^T + b_b
__device__ float g_u  [2][(size_t)Nn*G4];   // Whh @ h_node per node
__device__ float g_c  [2][(size_t)Nn*Hh];   // c_node per node
__device__ float g_arcA[(size_t)Ee*Hh];     // fwd arc_h (== ef, edge layout)
__device__ float g_arcB[(size_t)Ee*Hh];     // bwd arc_h at [node][slot]
__device__ float g_z  [2][(size_t)Nn*Dd*Aa];// attention preactivation accumulators
__device__ float g_hid[(size_t)Ee*Hh];      // decoder hidden
__device__ int   g_cz[2][Nn];
__device__ int   g_cu[2][Nn];

// ---------------- helpers ----------------
__device__ __forceinline__ int ld_acq(const int* p){
    int v; asm volatile("ld.acquire.gpu.b32 %0,[%1];":"=r"(v):"l"(p):"memory"); return v;
}
__device__ __forceinline__ void red_rel(int* p){
    asm volatile("red.release.gpu.global.add.s32 [%0], 1;"::"l"(p):"memory");
}
__device__ __forceinline__ float sigf(float x){ return 1.f/(1.f+expf(-x)); }

// ---------------- init: counters + z-seed (ba + x[:3] @ Wa[:,512:515]^T) ---
__global__ void init_kernel(const float* __restrict__ edges,
                            const float* __restrict__ Wa,
                            const float* __restrict__ ba)
{
    int idx = blockIdx.x*256 + threadIdx.x;        // 0 .. 2^22-1
    if (idx < Nn){
        g_cz[0][idx]=0; g_cz[1][idx]=0; g_cu[0][idx]=0; g_cu[1][idx]=0;
    }
    int dir = idx >> 21;
    int rem = idx & ((1<<21)-1);
    int i = rem >> 8;
    int d = (rem >> 6) & 3;
    int a = rem & 63;
    float z = ba[a];
    size_t e = 0; bool ok = true;
    if (dir == 0) e = (size_t)i*4 + d;
    else { int cn = i+1+d; if (cn < Nn) e = (size_t)cn*4 + d; else ok = false; }
    if (ok){
        const float* x  = edges + e*Ff;
        const float* wr = Wa + (size_t)a*(Hh+3) + Hh;
        z += x[0]*wr[0] + x[1]*wr[1] + x[2]*wr[2];
    }
    g_z[dir][((size_t)i*4 + d)*Aa + a] = z;
}

// ------------- SGEMM: C[M,Nc] = A[M,K] @ B[Nc,K]^T + bias (opt relu) -------
// mode 0: plain A.  mode 1: A rows are feat[e] = [ef[e] | eb[e]] gathered.
__global__ void __launch_bounds__(256) gemm_kernel(
    const float* __restrict__ A, const float* __restrict__ B,
    const float* __restrict__ bias, float* __restrict__ C,
    int M, int Nc, int K, int mode)
{
    __shared__ float sA[16][132];
    __shared__ float sB[16][132];
    int tid = threadIdx.x;
    int n0 = blockIdx.x * 128;
    int m0 = blockIdx.y * 128;
    int tx = tid & 15, ty = tid >> 4;
    float acc[8][8];
    #pragma unroll
    for (int ii=0; ii<8; ii++)
        #pragma unroll
        for (int jj=0; jj<8; jj++) acc[ii][jj] = 0.f;

    for (int k0 = 0; k0 < K; k0 += 16){
        #pragma unroll
        for (int u = 0; u < 2; u++){
            int v = tid + u*256;
            int row = v >> 2, kq = v & 3;
            float4 va;
            if (mode == 0){
                va = *(const float4*)(A + (size_t)(m0+row)*K + k0 + kq*4);
            } else {
                int e = m0 + row;
                int kk = k0 + kq*4;
                if (kk < Hh){
                    va = *(const float4*)(g_arcA + (size_t)e*Hh + kk);
                } else {
                    int d = e & 3, j = e >> 2;
                    if (j >= 1+d)
                        va = *(const float4*)(g_arcB + (size_t)(e - 4*(1+d))*Hh + (kk - Hh));
                    else
                        va = make_float4(0.f,0.f,0.f,0.f);
                }
            }
            sA[kq*4+0][row]=va.x; sA[kq*4+1][row]=va.y;
            sA[kq*4+2][row]=va.z; sA[kq*4+3][row]=va.w;
            float4 vb = *(const float4*)(B + (size_t)(n0+row)*K + k0 + kq*4);
            sB[kq*4+0][row]=vb.x; sB[kq*4+1][row]=vb.y;
            sB[kq*4+2][row]=vb.z; sB[kq*4+3][row]=vb.w;
        }
        __syncthreads();
        #pragma unroll
        for (int k=0; k<16; k++){
            float4 a0 = *(const float4*)&sA[k][ty*8];
            float4 a1 = *(const float4*)&sA[k][ty*8+4];
            float4 b0 = *(const float4*)&sB[k][tx*8];
            float4 b1 = *(const float4*)&sB[k][tx*8+4];
            float av[8] = {a0.x,a0.y,a0.z,a0.w,a1.x,a1.y,a1.z,a1.w};
            float bv[8] = {b0.x,b0.y,b0.z,b0.w,b1.x,b1.y,b1.z,b1.w};
            #pragma unroll
            for (int ii=0; ii<8; ii++)
                #pragma unroll
                for (int jj=0; jj<8; jj++)
                    acc[ii][jj] = fmaf(av[ii], bv[jj], acc[ii][jj]);
        }
        __syncthreads();
    }
    #pragma unroll
    for (int ii=0; ii<8; ii++){
        int m = m0 + ty*8 + ii;
        #pragma unroll
        for (int jj=0; jj<8; jj++){
            int n = n0 + tx*8 + jj;
            float v = acc[ii][jj] + bias[n];
            if (mode == 1) v = fmaxf(v, 0.f);
            C[(size_t)m*Nc + n] = v;
        }
    }
}

// ---------------- persistent bidirectional recurrence ----------------------
__global__ void __launch_bounds__(256, 1) recur_kernel(
    const float* __restrict__ Whh_f, const float* __restrict__ Whh_b,
    const float* __restrict__ Wa, const float* __restrict__ Wao,
    const float* __restrict__ bao)
{
    const int dir = blockIdx.x >> 6;
    const int ct  = blockIdx.x & 63;
    const int tid = threadIdx.x;
    const int w = tid >> 5, l = tid & 31;

    const float* Whh = dir ? Whh_b : Whh_f;
    const float* preX = dir ? g_preB : g_preF;
    float* uArr = g_u[dir];
    float* cArr = g_c[dir];
    float* arc  = dir ? g_arcB : g_arcA;
    float* zArr = g_z[dir];
    int* cz = g_cz[dir];
    int* cu = g_cu[dir];

    __shared__ float sWa[8][64];
    __shared__ float sWao[64];
    __shared__ float sbao;
    __shared__ float h_s[4][8];
    __shared__ float carc_s[4][8];
    __shared__ float zs[256];
    __shared__ float logit_s[4];

    for (int x = tid; x < 512; x += 256){
        int q = x >> 6, a = x & 63;
        sWa[q][a] = Wa[(size_t)a*(Hh+3) + ct*8 + q];
    }
    if (tid < 64) sWao[tid] = Wao[tid];
    if (tid == 0) sbao = bao[0];

    // register-resident Whh slice: warp w owns rows R0..R0+3, lane l owns k=l*16..+15
    const int R0 = ct*32 + w*4;
    float4 wreg[4][4];
    #pragma unroll
    for (int r=0; r<4; r++)
        #pragma unroll
        for (int q=0; q<4; q++)
            wreg[r][q] = *(const float4*)(Whh + (size_t)(R0+r)*Hh + l*16 + q*4);
    __syncthreads();

    for (int t = 0; t < Nn; t++){
        const int i = dir ? (Nn-1-t) : t;
        if (t > 0){
            int ip = dir ? i+1 : i-1;
            if (tid == 0) while (ld_acq(&cu[ip]) < NCTA) {}
            __syncthreads();
        }

        // -------- Phase A: cell for this CTA's 8 h-elements x 4 arcs (warp 0)
        if (w == 0){
            int d = l >> 3, q = l & 7;
            int jj = ct*8 + q;
            bool valid = dir ? (i+1+d < Nn) : (i-1-d >= 0);
            float ha = 0.f, ca = 0.f;
            if (valid){
                int p = dir ? (i+1+d) : (i-1-d);
                size_t e = dir ? ((size_t)(i+1+d)*4 + d) : ((size_t)i*4 + d);
                const float* pr = preX + e*G4;
                const float* uu = uArr + (size_t)p*G4;
                float gi = pr[jj]        + __ldcg(uu + jj);
                float gf = pr[Hh+jj]     + __ldcg(uu + Hh+jj);
                float gg = pr[2*Hh+jj]   + __ldcg(uu + 2*Hh+jj);
                float go = pr[3*Hh+jj]   + __ldcg(uu + 3*Hh+jj);
                float cp = __ldcg(cArr + (size_t)p*Hh + jj);
                ca = sigf(gf)*cp + sigf(gi)*tanhf(gg);
                ha = sigf(go)*tanhf(ca);
            }
            h_s[d][q] = ha; carc_s[d][q] = ca;
            arc[((size_t)i*4 + d)*Hh + jj] = ha;
        }
        __syncthreads();

        // -------- Phase A-z: partial attention preactivations (all threads)
        {
            int d = tid >> 6, a = tid & 63;
            float v = 0.f;
            #pragma unroll
            for (int q=0; q<8; q++) v = fmaf(sWa[q][a], h_s[d][q], v);
            atomicAdd(&zArr[(size_t)i*256 + d*64 + a], v);
        }
        __syncthreads();
        if (tid == 0){
            red_rel(&cz[i]);
            while (ld_acq(&cz[i]) < NCTA) {}
        }
        __syncthreads();

        // -------- Phase B: logits + softmax weights (redundant per CTA)
        zs[tid] = __ldcg(&zArr[(size_t)i*256 + tid]);
        __syncthreads();
        if (tid < 4){
            float s = sbao;
            #pragma unroll
            for (int a=0; a<64; a++) s = fmaf(fmaxf(zs[tid*64+a], 0.f), sWao[a], s);
            logit_s[tid] = tanhf(s);
        }
        __syncthreads();
        float wgt[4];
        {
            bool vld[4]; float m = -1e30f; int nv = 0;
            #pragma unroll
            for (int d=0; d<4; d++){
                vld[d] = dir ? (i+1+d < Nn) : (i-1-d >= 0);
                if (vld[d]){ m = fmaxf(m, logit_s[d]); nv++; }
            }
            float ssum = 0.f;
            #pragma unroll
            for (int d=0; d<4; d++){
                float ev = vld[d] ? expf(logit_s[d]-m) : 0.f;
                wgt[d] = ev; ssum += ev;
            }
            if (nv){
                float inv = 1.f/ssum;
                #pragma unroll
                for (int d=0; d<4; d++) wgt[d] *= inv;
            }
        }

        // -------- Phase C: h_node slice (per lane k=l*16..+15), u = Whh@h_node
        float4 hn[4];
        #pragma unroll
        for (int q=0; q<4; q++) hn[q] = make_float4(0.f,0.f,0.f,0.f);
        #pragma unroll
        for (int d=0; d<4; d++){
            const float4* src = (const float4*)(arc + ((size_t)i*4 + d)*Hh + l*16);
            float wd = wgt[d];
            #pragma unroll
            for (int q=0; q<4; q++){
                float4 s = __ldcg(src + q);
                hn[q].x = fmaf(wd, s.x, hn[q].x);
                hn[q].y = fmaf(wd, s.y, hn[q].y);
                hn[q].z = fmaf(wd, s.z, hn[q].z);
                hn[q].w = fmaf(wd, s.w, hn[q].w);
            }
        }
        float acc[4] = {0.f,0.f,0.f,0.f};
        #pragma unroll
        for (int r=0; r<4; r++)
            #pragma unroll
            for (int q=0; q<4; q++){
                acc[r] = fmaf(wreg[r][q].x, hn[q].x, acc[r]);
                acc[r] = fmaf(wreg[r][q].y, hn[q].y, acc[r]);
                acc[r] = fmaf(wreg[r][q].z, hn[q].z, acc[r]);
                acc[r] = fmaf(wreg[r][q].w, hn[q].w, acc[r]);
            }
        #pragma unroll
        for (int off=16; off; off >>= 1){
            #pragma unroll
            for (int r=0; r<4; r++)
                acc[r] += __shfl_xor_sync(0xffffffffu, acc[r], off);
        }
        if (l < 4){
            float outv = (l==0)?acc[0]:(l==1)?acc[1]:(l==2)?acc[2]:acc[3];
            uArr[(size_t)i*G4 + R0 + l] = outv;
        }
        if (tid < 8){
            float c = 0.f;
            #pragma unroll
            for (int d=0; d<4; d++) c = fmaf(wgt[d], carc_s[d][tid], c);
            cArr[(size_t)i*Hh + ct*8 + tid] = c;
        }
        __syncthreads();
        if (tid == 0) red_rel(&cu[i]);
    }
}

// ---------------- final: out[e] = hid[e] . Wdo + bdo --------------------
__global__ void final_kernel(const float* __restrict__ Wdo,
                             const float* __restrict__ bdo,
                             float* __restrict__ out)
{
    int gw = (blockIdx.x*blockDim.x + threadIdx.x) >> 5;
    int l = threadIdx.x & 31;
    if (gw >= Ee) return;
    const float* h = g_hid + (size_t)gw*Hh;
    float s = 0.f;
    #pragma unroll
    for (int q=0; q<16; q++) s = fmaf(h[l + q*32], Wdo[l + q*32], s);
    #pragma unroll
    for (int off=16; off; off >>= 1) s += __shfl_xor_sync(0xffffffffu, s, off);
    if (l == 0) out[gw] = s + bdo[0];
}

// ---------------- launch --------------------------------------------------
extern "C" void kernel_launch(void* const* d_in, const int* in_sizes, int n_in,
                              void* d_out, int out_size)
{
    const float* edges = (const float*)d_in[0];
    const float* Wih_f = (const float*)d_in[1];
    const float* Whh_f = (const float*)d_in[2];
    const float* b_f   = (const float*)d_in[3];
    const float* Wih_b = (const float*)d_in[4];
    const float* Whh_b = (const float*)d_in[5];
    const float* b_b   = (const float*)d_in[6];
    const float* Wa    = (const float*)d_in[7];
    const float* ba    = (const float*)d_in[8];
    const float* Wao   = (const float*)d_in[9];
    const float* bao   = (const float*)d_in[10];
    const float* Wd    = (const float*)d_in[11];
    const float* bd    = (const float*)d_in[12];
    const float* Wdo   = (const float*)d_in[13];
    const float* bdo   = (const float*)d_in[14];
    float* out = (float*)d_out;

    float *preF, *preB, *hid;
    cudaGetSymbolAddress((void**)&preF, g_preF);
    cudaGetSymbolAddress((void**)&preB, g_preB);
    cudaGetSymbolAddress((void**)&hid,  g_hid);

    // 1. counters + z seed
    init_kernel<<<16384, 256>>>(edges, Wa, ba);
    // 2. input-side GEMMs: pre = edges @ Wih^T + b
    gemm_kernel<<<dim3(G4/128, Ee/128), 256>>>(edges, Wih_f, b_f, preF, Ee, G4, Ff, 0);
    gemm_kernel<<<dim3(G4/128, Ee/128), 256>>>(edges, Wih_b, b_b, preB, Ee, G4, Ff, 0);
    // 3. bidirectional recurrence (persistent, 128 CTAs)
    recur_kernel<<<2*NCTA, 256>>>(Whh_f, Whh_b, Wa, Wao, bao);
    // 4. decoder GEMM: hid = relu(feat @ Wd^T + bd), feat gathered from arcs
    gemm_kernel<<<dim3(Hh/128, Ee/128), 256>>>(nullptr, Wd, bd, hid, Ee, Hh, 2*Hh, 1);
    // 5. output projection
    final_kernel<<<(Ee*32)/256, 256>>>(Wdo, bdo, out);
}

// round 6
// speedup vs baseline: 1.5521x; 1.5124x over previous
#include <cuda_runtime.h>
#include <math.h>

#define Nn 8192
#define Dd 4
#define Ff 256
#define Hh 512
#define Aa 64
#define Ee (Nn*Dd)
#define G4 2048
#define NCTA 64
#define ZPAD 16   /* floats between z slots: 64B -> spreads atomics across LTS */
#define CPAD 32   /* ints per counter slot: own 128B line */

// ---------------- device scratch (no cudaMalloc allowed) ----------------
__device__ float g_preF[(size_t)Ee*G4];         // edges @ Wih_f^T + b_f
__device__ float g_preB[(size_t)Ee*G4];         // edges @ Wih_b^T + b_b
__device__ float g_u  [2][(size_t)Nn*G4];       // Whh @ h_node per node
__device__ float g_c  [2][(size_t)Nn*Hh];       // c_node per node
__device__ float g_arcA[(size_t)Ee*Hh];         // fwd arc_h (== ef, edge layout)
__device__ float g_arcB[(size_t)Ee*Hh];         // bwd arc_h at [node][slot]
__device__ float g_z  [2][(size_t)Nn*Dd*Aa*ZPAD]; // padded attention accumulators
__device__ float g_hid[(size_t)Ee*Hh];          // decoder hidden
__device__ int   g_cz[2][(size_t)Nn*CPAD];
__device__ int   g_cu[2][(size_t)Nn*CPAD];

// ---------------- helpers ----------------
__device__ __forceinline__ int ld_acq(const int* p){
    int v; asm volatile("ld.acquire.gpu.b32 %0,[%1];":"=r"(v):"l"(p):"memory"); return v;
}
__device__ __forceinline__ void red_rel(int* p){
    asm volatile("red.release.gpu.global.add.s32 [%0], 1;"::"l"(p):"memory");
}
__device__ __forceinline__ float sigf(float x){ return 1.f/(1.f+expf(-x)); }

// ---------------- init: counters + z-seed (ba + x[:3] @ Wa[:,512:515]^T) ---
__global__ void init_kernel(const float* __restrict__ edges,
                            const float* __restrict__ Wa,
                            const float* __restrict__ ba)
{
    int idx = blockIdx.x*256 + threadIdx.x;        // 0 .. 2^22-1
    if (idx < Nn*CPAD){
        g_cz[0][idx]=0; g_cz[1][idx]=0; g_cu[0][idx]=0; g_cu[1][idx]=0;
    }
    int dir = idx >> 21;
    int rem = idx & ((1<<21)-1);
    int i = rem >> 8;
    int d = (rem >> 6) & 3;
    int a = rem & 63;
    float z = ba[a];
    size_t e = 0; bool ok = true;
    if (dir == 0) e = (size_t)i*4 + d;
    else { int cn = i+1+d; if (cn < Nn) e = (size_t)cn*4 + d; else ok = false; }
    if (ok){
        const float* x  = edges + e*Ff;
        const float* wr = Wa + (size_t)a*(Hh+3) + Hh;
        z += x[0]*wr[0] + x[1]*wr[1] + x[2]*wr[2];
    }
    g_z[dir][((size_t)i*256 + d*64 + a)*ZPAD] = z;
}

// ------------- SGEMM: C[M,Nc] = A[M,K] @ B[Nc,K]^T + bias (opt relu) -------
// mode 0: plain A.  mode 1: A rows are feat[e] = [ef[e] | eb[e]] gathered.
__global__ void __launch_bounds__(256) gemm_kernel(
    const float* __restrict__ A, const float* __restrict__ B,
    const float* __restrict__ bias, float* __restrict__ C,
    int M, int Nc, int K, int mode)
{
    __shared__ float sA[16][132];
    __shared__ float sB[16][132];
    int tid = threadIdx.x;
    int n0 = blockIdx.x * 128;
    int m0 = blockIdx.y * 128;
    int tx = tid & 15, ty = tid >> 4;
    float acc[8][8];
    #pragma unroll
    for (int ii=0; ii<8; ii++)
        #pragma unroll
        for (int jj=0; jj<8; jj++) acc[ii][jj] = 0.f;

    for (int k0 = 0; k0 < K; k0 += 16){
        #pragma unroll
        for (int u = 0; u < 2; u++){
            int v = tid + u*256;
            int row = v >> 2, kq = v & 3;
            float4 va;
            if (mode == 0){
                va = *(const float4*)(A + (size_t)(m0+row)*K + k0 + kq*4);
            } else {
                int e = m0 + row;
                int kk = k0 + kq*4;
                if (kk < Hh){
                    va = *(const float4*)(g_arcA + (size_t)e*Hh + kk);
                } else {
                    int d = e & 3, j = e >> 2;
                    if (j >= 1+d)
                        va = *(const float4*)(g_arcB + (size_t)(e - 4*(1+d))*Hh + (kk - Hh));
                    else
                        va = make_float4(0.f,0.f,0.f,0.f);
                }
            }
            sA[kq*4+0][row]=va.x; sA[kq*4+1][row]=va.y;
            sA[kq*4+2][row]=va.z; sA[kq*4+3][row]=va.w;
            float4 vb = *(const float4*)(B + (size_t)(n0+row)*K + k0 + kq*4);
            sB[kq*4+0][row]=vb.x; sB[kq*4+1][row]=vb.y;
            sB[kq*4+2][row]=vb.z; sB[kq*4+3][row]=vb.w;
        }
        __syncthreads();
        #pragma unroll
        for (int k=0; k<16; k++){
            float4 a0 = *(const float4*)&sA[k][ty*8];
            float4 a1 = *(const float4*)&sA[k][ty*8+4];
            float4 b0 = *(const float4*)&sB[k][tx*8];
            float4 b1 = *(const float4*)&sB[k][tx*8+4];
            float av[8] = {a0.x,a0.y,a0.z,a0.w,a1.x,a1.y,a1.z,a1.w};
            float bv[8] = {b0.x,b0.y,b0.z,b0.w,b1.x,b1.y,b1.z,b1.w};
            #pragma unroll
            for (int ii=0; ii<8; ii++)
                #pragma unroll
                for (int jj=0; jj<8; jj++)
                    acc[ii][jj] = fmaf(av[ii], bv[jj], acc[ii][jj]);
        }
        __syncthreads();
    }
    #pragma unroll
    for (int ii=0; ii<8; ii++){
        int m = m0 + ty*8 + ii;
        #pragma unroll
        for (int jj=0; jj<8; jj++){
            int n = n0 + tx*8 + jj;
            float v = acc[ii][jj] + bias[n];
            if (mode == 1) v = fmaxf(v, 0.f);
            C[(size_t)m*Nc + n] = v;
        }
    }
}

// ---------------- persistent bidirectional recurrence ----------------------
__global__ void __launch_bounds__(256, 1) recur_kernel(
    const float* __restrict__ Whh_f, const float* __restrict__ Whh_b,
    const float* __restrict__ Wa, const float* __restrict__ Wao,
    const float* __restrict__ bao)
{
    const int dir = blockIdx.x >> 6;
    const int ct  = blockIdx.x & 63;
    const int tid = threadIdx.x;
    const int w = tid >> 5, l = tid & 31;

    const float* Whh = dir ? Whh_b : Whh_f;
    const float* preX = dir ? g_preB : g_preF;
    float* uArr = g_u[dir];
    float* cArr = g_c[dir];
    float* arc  = dir ? g_arcB : g_arcA;
    float* zArr = g_z[dir];
    int* cz = g_cz[dir];
    int* cu = g_cu[dir];

    __shared__ float sWa[8][64];
    __shared__ float sWao[64];
    __shared__ float sbao;
    __shared__ float h_s[4][8];
    __shared__ float carc_s[4][8];
    __shared__ float zs[256];
    __shared__ float logit_s[4];
    __shared__ __align__(16) float hn_s[512];

    for (int x = tid; x < 512; x += 256){
        int q = x >> 6, a = x & 63;
        sWa[q][a] = Wa[(size_t)a*(Hh+3) + ct*8 + q];
    }
    if (tid < 64) sWao[tid] = Wao[tid];
    if (tid == 0) sbao = bao[0];

    // register-resident Whh slice: warp w owns rows R0..R0+3, lane l owns k=l*16..+15
    const int R0 = ct*32 + w*4;
    float4 wreg[4][4];
    #pragma unroll
    for (int r=0; r<4; r++)
        #pragma unroll
        for (int q=0; q<4; q++)
            wreg[r][q] = *(const float4*)(Whh + (size_t)(R0+r)*Hh + l*16 + q*4);
    __syncthreads();

    for (int t = 0; t < Nn; t++){
        const int i = dir ? (Nn-1-t) : t;

        // ---- prefetch pre-gate inputs (barrier-independent) -------------
        int dA = l >> 3, qA = l & 7;
        int jj = ct*8 + qA;
        bool valid = false; int p = 0; size_t eA = 0;
        float pg0=0.f, pg1=0.f, pg2=0.f, pg3=0.f;
        if (w == 0){
            valid = dir ? (i+1+dA < Nn) : (i-1-dA >= 0);
            if (valid){
                p  = dir ? (i+1+dA) : (i-1-dA);
                eA = dir ? ((size_t)(i+1+dA)*4 + dA) : ((size_t)i*4 + dA);
                const float* pr = preX + eA*G4;
                pg0 = __ldg(pr + jj);
                pg1 = __ldg(pr + Hh + jj);
                pg2 = __ldg(pr + 2*Hh + jj);
                pg3 = __ldg(pr + 3*Hh + jj);
            }
        }

        // ---- wait for u[prev], c[prev] ----------------------------------
        if (t > 0){
            int ip = dir ? i+1 : i-1;
            if (tid == 0) while (ld_acq(&cu[(size_t)ip*CPAD]) < NCTA) {}
            __syncthreads();
        }

        // ---- Phase A: cell for this CTA's 8 h-dims x 4 arcs (warp 0) ----
        if (w == 0){
            float ha = 0.f, ca = 0.f;
            if (valid){
                const float* uu = uArr + (size_t)p*G4;
                float gi = pg0 + __ldcg(uu + jj);
                float gf = pg1 + __ldcg(uu + Hh+jj);
                float gg = pg2 + __ldcg(uu + 2*Hh+jj);
                float go = pg3 + __ldcg(uu + 3*Hh+jj);
                float cp = __ldcg(cArr + (size_t)p*Hh + jj);
                ca = sigf(gf)*cp + sigf(gi)*tanhf(gg);
                ha = sigf(go)*tanhf(ca);
            }
            h_s[dA][qA] = ha; carc_s[dA][qA] = ca;
            arc[((size_t)i*4 + dA)*Hh + jj] = ha;
        }
        __syncthreads();

        // ---- Phase A-z: partial attention preactivations (all threads) --
        {
            int d = tid >> 6, a = tid & 63;
            float v = 0.f;
            #pragma unroll
            for (int q=0; q<8; q++) v = fmaf(sWa[q][a], h_s[d][q], v);
            atomicAdd(&zArr[((size_t)i*256 + d*64 + a)*ZPAD], v);
        }
        __syncthreads();
        if (tid == 0){
            red_rel(&cz[(size_t)i*CPAD]);
            while (ld_acq(&cz[(size_t)i*CPAD]) < NCTA) {}
        }
        __syncthreads();

        // ---- load z + arc slices (non-redundant) ------------------------
        zs[tid] = __ldcg(&zArr[((size_t)i*256 + tid)*ZPAD]);
        float2 av[4];
        {
            int k2 = tid*2;
            #pragma unroll
            for (int d=0; d<4; d++)
                av[d] = __ldcg((const float2*)(arc + ((size_t)i*4 + d)*Hh + k2));
        }
        __syncthreads();

        // ---- logits: warp-parallel reduce (warps 0..3, arc = w) ---------
        if (w < 4){
            float s = fmaxf(zs[w*64 + l], 0.f)      * sWao[l]
                    + fmaxf(zs[w*64 + l + 32], 0.f) * sWao[l + 32];
            #pragma unroll
            for (int off=16; off; off >>= 1) s += __shfl_xor_sync(0xffffffffu, s, off);
            if (l == 0) logit_s[w] = tanhf(s + sbao);
        }
        __syncthreads();

        // ---- softmax weights (redundant per thread) ---------------------
        float wgt[4];
        {
            bool vld[4]; float m = -1e30f; int nv = 0;
            #pragma unroll
            for (int d=0; d<4; d++){
                vld[d] = dir ? (i+1+d < Nn) : (i-1-d >= 0);
                if (vld[d]){ m = fmaxf(m, logit_s[d]); nv++; }
            }
            float ssum = 0.f;
            #pragma unroll
            for (int d=0; d<4; d++){
                float ev = vld[d] ? expf(logit_s[d]-m) : 0.f;
                wgt[d] = ev; ssum += ev;
            }
            if (nv){
                float inv = 1.f/ssum;
                #pragma unroll
                for (int d=0; d<4; d++) wgt[d] *= inv;
            }
        }

        // ---- h_node into smem (each thread: its 2 k-values) -------------
        {
            int k2 = tid*2;
            float h0 = 0.f, h1 = 0.f;
            #pragma unroll
            for (int d=0; d<4; d++){
                h0 = fmaf(wgt[d], av[d].x, h0);
                h1 = fmaf(wgt[d], av[d].y, h1);
            }
            hn_s[k2] = h0; hn_s[k2+1] = h1;
        }
        if (tid < 8){
            float c = 0.f;
            #pragma unroll
            for (int d=0; d<4; d++) c = fmaf(wgt[d], carc_s[d][tid], c);
            cArr[(size_t)i*Hh + ct*8 + tid] = c;
        }
        __syncthreads();

        // ---- u = Whh @ h_node (rows R0..R0+3 per warp, smem h) ----------
        float acc[4] = {0.f,0.f,0.f,0.f};
        #pragma unroll
        for (int q=0; q<4; q++){
            float4 hv = *(const float4*)&hn_s[l*16 + q*4];
            #pragma unroll
            for (int r=0; r<4; r++){
                acc[r] = fmaf(wreg[r][q].x, hv.x, acc[r]);
                acc[r] = fmaf(wreg[r][q].y, hv.y, acc[r]);
                acc[r] = fmaf(wreg[r][q].z, hv.z, acc[r]);
                acc[r] = fmaf(wreg[r][q].w, hv.w, acc[r]);
            }
        }
        #pragma unroll
        for (int off=16; off; off >>= 1){
            #pragma unroll
            for (int r=0; r<4; r++)
                acc[r] += __shfl_xor_sync(0xffffffffu, acc[r], off);
        }
        if (l < 4){
            float outv = (l==0)?acc[0]:(l==1)?acc[1]:(l==2)?acc[2]:acc[3];
            uArr[(size_t)i*G4 + R0 + l] = outv;
        }
        __syncthreads();
        if (tid == 0) red_rel(&cu[(size_t)i*CPAD]);
    }
}

// ---------------- final: out[e] = hid[e] . Wdo + bdo --------------------
__global__ void final_kernel(const float* __restrict__ Wdo,
                             const float* __restrict__ bdo,
                             float* __restrict__ out)
{
    int gw = (blockIdx.x*blockDim.x + threadIdx.x) >> 5;
    int l = threadIdx.x & 31;
    if (gw >= Ee) return;
    const float* h = g_hid + (size_t)gw*Hh;
    float s = 0.f;
    #pragma unroll
    for (int q=0; q<16; q++) s = fmaf(h[l + q*32], Wdo[l + q*32], s);
    #pragma unroll
    for (int off=16; off; off >>= 1) s += __shfl_xor_sync(0xffffffffu, s, off);
    if (l == 0) out[gw] = s + bdo[0];
}

// ---------------- launch --------------------------------------------------
extern "C" void kernel_launch(void* const* d_in, const int* in_sizes, int n_in,
                              void* d_out, int out_size)
{
    const float* edges = (const float*)d_in[0];
    const float* Wih_f = (const float*)d_in[1];
    const float* Whh_f = (const float*)d_in[2];
    const float* b_f   = (const float*)d_in[3];
    const float* Wih_b = (const float*)d_in[4];
    const float* Whh_b = (const float*)d_in[5];
    const float* b_b   = (const float*)d_in[6];
    const float* Wa    = (const float*)d_in[7];
    const float* ba    = (const float*)d_in[8];
    const float* Wao   = (const float*)d_in[9];
    const float* bao   = (const float*)d_in[10];
    const float* Wd    = (const float*)d_in[11];
    const float* bd    = (const float*)d_in[12];
    const float* Wdo   = (const float*)d_in[13];
    const float* bdo   = (const float*)d_in[14];
    float* out = (float*)d_out;

    float *preF, *preB, *hid;
    cudaGetSymbolAddress((void**)&preF, g_preF);
    cudaGetSymbolAddress((void**)&preB, g_preB);
    cudaGetSymbolAddress((void**)&hid,  g_hid);

    // 1. counters + z seed
    init_kernel<<<16384, 256>>>(edges, Wa, ba);
    // 2. input-side GEMMs: pre = edges @ Wih^T + b
    gemm_kernel<<<dim3(G4/128, Ee/128), 256>>>(edges, Wih_f, b_f, preF, Ee, G4, Ff, 0);
    gemm_kernel<<<dim3(G4/128, Ee/128), 256>>>(edges, Wih_b, b_b, preB, Ee, G4, Ff, 0);
    // 3. bidirectional recurrence (persistent, 128 CTAs)
    recur_kernel<<<2*NCTA, 256>>>(Whh_f, Whh_b, Wa, Wao, bao);
    // 4. decoder GEMM: hid = relu(feat @ Wd^T + bd), feat gathered from arcs
    gemm_kernel<<<dim3(Hh/128, Ee/128), 256>>>(nullptr, Wd, bd, hid, Ee, Hh, 2*Hh, 1);
    // 5. output projection
    final_kernel<<<(Ee*32)/256, 256>>>(Wdo, bdo, out);
}